// round 6
// baseline (speedup 1.0000x reference)
#include <cuda_runtime.h>
#include <cuda_bf16.h>
#include <math.h>
#include <stdint.h>

// ---------------- problem constants ----------------
#define S_LEN 2048
#define D_MODEL 2048
#define N_HEADS 16
#define N_KV 8
#define HEAD_DIM 128
#define INTER 6144
#define N_LAYERS 2
#define EPS 1e-6f
#define ATT_SCALE 0.08838834764831845f

#define K3_D (3 * D_MODEL)   // 6144
#define K3_I (3 * INTER)     // 18432
#define QKV_N 4096           // q(2048) + k(1024) + v(1024)

// ---------------- scratch (device globals, no allocs) ----------------
__device__ float g_qkv[S_LEN * QKV_N];
__device__ float g_gate[S_LEN * INTER];
__device__ __nv_bfloat16 a3_x[S_LEN * K3_D];
__device__ __nv_bfloat16 a3_ctx[S_LEN * K3_D];
__device__ __nv_bfloat16 a3_mlp[S_LEN * K3_I];

__device__ __nv_bfloat16 w3_qkv[N_LAYERS * QKV_N * K3_D];
__device__ __nv_bfloat16 w3_o[N_LAYERS * D_MODEL * K3_D];
__device__ __nv_bfloat16 w3_gate[N_LAYERS * INTER * K3_D];
__device__ __nv_bfloat16 w3_up[N_LAYERS * INTER * K3_D];
__device__ __nv_bfloat16 w3_down[N_LAYERS * D_MODEL * K3_I];

// ---------------- helpers ----------------
__device__ __forceinline__ uint32_t pack_bf2(float x, float y)
{
    __nv_bfloat162 v = __floats2bfloat162_rn(x, y);
    return *(uint32_t*)&v;
}

// ---------------- weight conversion: W[rows][K] fp32 -> [bh|bh|bl] bf16 ----------------
__global__ void wconv_kernel(const float2* __restrict__ src,
                             __nv_bfloat16* __restrict__ dst,
                             int rows, int K)
{
    int half = K >> 1;
    int total = rows * half;
    for (int i = blockIdx.x * blockDim.x + threadIdx.x; i < total;
         i += gridDim.x * blockDim.x) {
        int n = i / half, k2 = i - n * half;
        float2 v = src[(size_t)n * half + k2];
        __nv_bfloat16 h0 = __float2bfloat16_rn(v.x);
        __nv_bfloat16 h1 = __float2bfloat16_rn(v.y);
        float l0 = v.x - __bfloat162float(h0);
        float l1 = v.y - __bfloat162float(h1);
        uint32_t hh; { __nv_bfloat162 t; t.x = h0; t.y = h1; hh = *(uint32_t*)&t; }
        uint32_t ll = pack_bf2(l0, l1);
        __nv_bfloat16* row = dst + (size_t)n * (3 * K);
        *(uint32_t*)&row[2 * k2]         = hh;
        *(uint32_t*)&row[K + 2 * k2]     = hh;
        *(uint32_t*)&row[2 * K + 2 * k2] = ll;
    }
}

// ---------------- embedding gather ----------------
__global__ void embed_kernel(const int* __restrict__ ids,
                             const float* __restrict__ embed,
                             float* __restrict__ h)
{
    int s = blockIdx.x;
    int id = ids[s];
    const float4* src = (const float4*)(embed + (size_t)id * D_MODEL);
    float4* dst = (float4*)(h + (size_t)s * D_MODEL);
    for (int i = threadIdx.x; i < D_MODEL / 4; i += blockDim.x)
        dst[i] = src[i];
}

// ---------------- RMSNorm -> triple-bf16 [ah|al|ah] ----------------
__global__ void rmsnorm_t_kernel(const float* __restrict__ in,
                                 const float* __restrict__ sc,
                                 __nv_bfloat16* __restrict__ out3)
{
    int row = blockIdx.x;
    const float* p = in + (size_t)row * D_MODEL;
    float ss = 0.f;
    for (int d = threadIdx.x; d < D_MODEL; d += blockDim.x) {
        float v = p[d];
        ss = fmaf(v, v, ss);
    }
    #pragma unroll
    for (int o = 16; o > 0; o >>= 1) ss += __shfl_xor_sync(0xFFFFFFFFu, ss, o);
    __shared__ float red[8];
    int lane = threadIdx.x & 31, wid = threadIdx.x >> 5;
    if (lane == 0) red[wid] = ss;
    __syncthreads();
    float tot = 0.f;
    #pragma unroll
    for (int i = 0; i < 8; i++) tot += red[i];
    float r = rsqrtf(tot * (1.0f / D_MODEL) + EPS);
    __nv_bfloat16* orow = out3 + (size_t)row * K3_D;
    for (int d2 = threadIdx.x; d2 < D_MODEL / 2; d2 += blockDim.x) {
        int d = d2 * 2;
        float v0 = p[d] * r * sc[d];
        float v1 = p[d + 1] * r * sc[d + 1];
        __nv_bfloat16 h0 = __float2bfloat16_rn(v0);
        __nv_bfloat16 h1 = __float2bfloat16_rn(v1);
        uint32_t hh; { __nv_bfloat162 t; t.x = h0; t.y = h1; hh = *(uint32_t*)&t; }
        uint32_t ll = pack_bf2(v0 - __bfloat162float(h0), v1 - __bfloat162float(h1));
        *(uint32_t*)&orow[d]               = hh;
        *(uint32_t*)&orow[D_MODEL + d]     = ll;
        *(uint32_t*)&orow[2 * D_MODEL + d] = hh;
    }
}

// ---------------- per-head QK RMSNorm + RoPE (fused qkv buffer) ----------------
__global__ void qknorm_rope_kernel(float* __restrict__ qkv,
                                   const float* __restrict__ qn, const float* __restrict__ kn,
                                   const float* __restrict__ cosb, const float* __restrict__ sinb)
{
    int s = blockIdx.x;
    int head = blockIdx.y;
    float* vec;
    const float* sc;
    if (head < N_HEADS) {
        vec = qkv + (size_t)s * QKV_N + head * HEAD_DIM;
        sc = qn;
    } else {
        vec = qkv + (size_t)s * QKV_N + 2048 + (head - N_HEADS) * HEAD_DIM;
        sc = kn;
    }
    int d = threadIdx.x;
    float v = vec[d];
    float ss = v * v;
    #pragma unroll
    for (int o = 16; o > 0; o >>= 1) ss += __shfl_xor_sync(0xFFFFFFFFu, ss, o);
    __shared__ float red[4];
    int lane = d & 31, wid = d >> 5;
    if (lane == 0) red[wid] = ss;
    __syncthreads();
    float tot = red[0] + red[1] + red[2] + red[3];
    float nv = v * rsqrtf(tot * (1.0f / HEAD_DIM) + EPS) * sc[d];
    __shared__ float tmp[HEAD_DIM];
    tmp[d] = nv;
    __syncthreads();
    float rot = (d < 64) ? -tmp[d + 64] : tmp[d - 64];
    vec[d] = nv * cosb[(size_t)s * HEAD_DIM + d] + rot * sinb[(size_t)s * HEAD_DIM + d];
}

// ---------------- causal flash attention (fp32) -> triple-bf16 ctx ----------------
__global__ void __launch_bounds__(128) attn_kernel(
    const float* __restrict__ qkv, __nv_bfloat16* __restrict__ ctx3)
{
    __shared__ alignas(16) float q_sh[32][129];
    __shared__ alignas(16) float kvT[128][36];
    __shared__ alignas(16) float p_sh[32][33];
    __shared__ float m_sh[32], l_sh[32], al_sh[32];

    const int tid = threadIdx.x;
    const int qt = blockIdx.x, h = blockIdx.y;
    const int kvh = h >> 1;
    const int q0 = qt * 32;
    const int qr = tid & 31, grp = tid >> 5;
    const int d0 = grp * 32;

    const float* qb = qkv + h * HEAD_DIM;
    const float* kb = qkv + 2048 + kvh * HEAD_DIM;
    const float* vb = qkv + 3072 + kvh * HEAD_DIM;

    for (int i = tid; i < 32 * 128; i += 128) {
        int r = i >> 7, d = i & 127;
        q_sh[r][d] = qb[(size_t)(q0 + r) * QKV_N + d];
    }
    if (tid < 32) { m_sh[tid] = -1e30f; l_sh[tid] = 0.f; }
    float acc[32];
    #pragma unroll
    for (int j = 0; j < 32; j++) acc[j] = 0.f;

    const int nch = qt + 1;
    for (int c = 0; c < nch; c++) {
        const int k0 = c * 32;
        __syncthreads();
        for (int i = tid; i < 32 * 128; i += 128) {
            int r = i >> 7, d = i & 127;
            kvT[d][r] = kb[(size_t)(k0 + r) * QKV_N + d];
        }
        __syncthreads();
        float sc[8];
        #pragma unroll
        for (int jj = 0; jj < 8; jj++) sc[jj] = 0.f;
        for (int d = 0; d < 128; d++) {
            float qv = q_sh[qr][d];
            const float4 ka = *(const float4*)&kvT[d][grp * 8];
            const float4 kbv = *(const float4*)&kvT[d][grp * 8 + 4];
            sc[0] = fmaf(qv, ka.x, sc[0]);
            sc[1] = fmaf(qv, ka.y, sc[1]);
            sc[2] = fmaf(qv, ka.z, sc[2]);
            sc[3] = fmaf(qv, ka.w, sc[3]);
            sc[4] = fmaf(qv, kbv.x, sc[4]);
            sc[5] = fmaf(qv, kbv.y, sc[5]);
            sc[6] = fmaf(qv, kbv.z, sc[6]);
            sc[7] = fmaf(qv, kbv.w, sc[7]);
        }
        #pragma unroll
        for (int jj = 0; jj < 8; jj++) {
            int kk = grp * 8 + jj;
            float s = sc[jj] * ATT_SCALE;
            if (k0 + kk > q0 + qr) s = -1e30f;
            p_sh[qr][kk] = s;
        }
        __syncthreads();
        if (tid < 32) {
            float mold = m_sh[tid], m = mold;
            #pragma unroll
            for (int kk = 0; kk < 32; kk++) m = fmaxf(m, p_sh[tid][kk]);
            float alpha = __expf(mold - m);
            float rs = 0.f;
            #pragma unroll
            for (int kk = 0; kk < 32; kk++) {
                float p = __expf(p_sh[tid][kk] - m);
                p_sh[tid][kk] = p;
                rs += p;
            }
            m_sh[tid] = m;
            l_sh[tid] = l_sh[tid] * alpha + rs;
            al_sh[tid] = alpha;
        }
        __syncthreads();
        for (int i = tid; i < 32 * 128; i += 128) {
            int r = i >> 7, d = i & 127;
            kvT[d][r] = vb[(size_t)(k0 + r) * QKV_N + d];
        }
        __syncthreads();
        float pr[32];
        #pragma unroll
        for (int kk = 0; kk < 32; kk++) pr[kk] = p_sh[qr][kk];
        float alpha = al_sh[qr];
        #pragma unroll
        for (int j = 0; j < 32; j++) acc[j] *= alpha;
        #pragma unroll
        for (int j = 0; j < 32; j++) {
            const float* vrow = &kvT[d0 + j][0];
            float s0 = 0.f;
            #pragma unroll
            for (int kk = 0; kk < 32; kk++) s0 = fmaf(pr[kk], vrow[kk], s0);
            acc[j] += s0;
        }
    }
    __syncthreads();
    float inv = 1.0f / l_sh[qr];
    __nv_bfloat16* orow = ctx3 + (size_t)(q0 + qr) * K3_D + h * HEAD_DIM + d0;
    #pragma unroll
    for (int j = 0; j < 32; j += 2) {
        float v0 = acc[j] * inv;
        float v1 = acc[j + 1] * inv;
        __nv_bfloat16 h0 = __float2bfloat16_rn(v0);
        __nv_bfloat16 h1 = __float2bfloat16_rn(v1);
        uint32_t hh; { __nv_bfloat162 t; t.x = h0; t.y = h1; hh = *(uint32_t*)&t; }
        uint32_t ll = pack_bf2(v0 - __bfloat162float(h0), v1 - __bfloat162float(h1));
        *(uint32_t*)&orow[j]               = hh;
        *(uint32_t*)&orow[D_MODEL + j]     = ll;
        *(uint32_t*)&orow[2 * D_MODEL + j] = hh;
    }
}

// ============================================================
// bf16 GEMM (mma.sync): C[M,N] = A3[M,K3] @ B3[N,K3]^T
// Block 128x256, 256 threads (8 warps, 2M x 4N), WARP TILE 64x64.
// cp.async 4-stage pipeline, BK=64 bf16 per chunk, wait_group 2.
// MODE 0: C = acc ; 1: C += acc ; 2: C = silu(acc)
// MODE 5: C3 = triple_bf16(G * acc)
// ============================================================
#define BM 128
#define BN 256
#define BK 64
#define SROW 72             // halfs per smem row (64 + 8 pad)
#define GSTAGES 4
#define A_ST_HALFS (BM * SROW)
#define B_ST_HALFS (BN * SROW)
#define ST_HALFS (A_ST_HALFS + B_ST_HALFS)
#define GEMM_SMEM (GSTAGES * ST_HALFS * 2)

__device__ __forceinline__ void mma_bf16(
    float& c0, float& c1, float& c2, float& c3,
    uint32_t a0, uint32_t a1, uint32_t a2, uint32_t a3,
    uint32_t b0, uint32_t b1)
{
    asm volatile(
        "mma.sync.aligned.m16n8k16.row.col.f32.bf16.bf16.f32 "
        "{%0,%1,%2,%3},{%4,%5,%6,%7},{%8,%9},{%0,%1,%2,%3};\n"
        : "+f"(c0), "+f"(c1), "+f"(c2), "+f"(c3)
        : "r"(a0), "r"(a1), "r"(a2), "r"(a3), "r"(b0), "r"(b1));
}

__device__ __forceinline__ void ldsm4(uint32_t addr, uint32_t& r0, uint32_t& r1,
                                      uint32_t& r2, uint32_t& r3)
{
    asm volatile("ldmatrix.sync.aligned.m8n8.x4.shared.b16 {%0,%1,%2,%3}, [%4];\n"
                 : "=r"(r0), "=r"(r1), "=r"(r2), "=r"(r3) : "r"(addr));
}

__device__ __forceinline__ uint32_t smem_u32(const void* p)
{
    uint32_t a;
    asm("{ .reg .u64 t; cvta.to.shared.u64 t, %1; cvt.u32.u64 %0, t; }"
        : "=r"(a) : "l"(p));
    return a;
}

__device__ __forceinline__ void cpasync16(uint32_t dst, const void* src)
{
    asm volatile("cp.async.cg.shared.global [%0], [%1], 16;\n"
                 :: "r"(dst), "l"(src) : "memory");
}

template <int MODE>
__global__ void __launch_bounds__(256, 1) hgemm3_kernel(
    const __nv_bfloat16* __restrict__ A3, const __nv_bfloat16* __restrict__ B3,
    float* __restrict__ C, const float* __restrict__ G,
    __nv_bfloat16* __restrict__ C3,
    int M, int N, int K3)
{
    extern __shared__ __align__(16) __nv_bfloat16 smem[];
    const int tid = threadIdx.x;
    const int lane = tid & 31;
    const int warp = tid >> 5;
    const int warp_m = warp & 1;   // 0..1 (64-row strips)
    const int warp_n = warp >> 1;  // 0..3 (64-col strips)
    const int m0 = blockIdx.y * BM;
    const int n0 = blockIdx.x * BN;
    const uint32_t sbase = smem_u32(smem);

    const __nv_bfloat16* Abase = A3 + (size_t)m0 * K3;
    const __nv_bfloat16* Bbase = B3 + (size_t)n0 * K3;
    const int nch = K3 >> 6;

    auto load_chunk = [&](int ch, int s) {
        uint32_t sa = sbase + (uint32_t)s * ST_HALFS * 2;
        uint32_t sb = sa + A_ST_HALFS * 2;
        const __nv_bfloat16* As = Abase + (size_t)ch * BK;
        const __nv_bfloat16* Bs = Bbase + (size_t)ch * BK;
        #pragma unroll
        for (int i = 0; i < 4; i++) {
            int u = tid + i * 256;
            int r = u >> 3, c8 = u & 7;
            cpasync16(sa + (uint32_t)(r * SROW + c8 * 8) * 2, As + (size_t)r * K3 + c8 * 8);
        }
        #pragma unroll
        for (int i = 0; i < 8; i++) {
            int u = tid + i * 256;
            int r = u >> 3, c8 = u & 7;
            cpasync16(sb + (uint32_t)(r * SROW + c8 * 8) * 2, Bs + (size_t)r * K3 + c8 * 8);
        }
        asm volatile("cp.async.commit_group;\n" ::: "memory");
    };

    float acc[4][8][4];
    #pragma unroll
    for (int i = 0; i < 4; i++)
        #pragma unroll
        for (int j = 0; j < 8; j++)
            #pragma unroll
            for (int r = 0; r < 4; r++) acc[i][j][r] = 0.f;

    load_chunk(0, 0);
    load_chunk(1, 1);
    load_chunk(2, 2);

    for (int ch = 0; ch < nch; ch++) {
        const int s = ch & (GSTAGES - 1);
        asm volatile("cp.async.wait_group 2;\n" ::: "memory");
        __syncthreads();
        if (ch + 3 < nch) load_chunk(ch + 3, (ch + 3) & (GSTAGES - 1));

        uint32_t sa = sbase + (uint32_t)s * ST_HALFS * 2;
        uint32_t sb = sa + A_ST_HALFS * 2;
        #pragma unroll
        for (int s16 = 0; s16 < 4; s16++) {
            uint32_t af[4][4];
            #pragma unroll
            for (int i = 0; i < 4; i++) {
                uint32_t ad = sa + (uint32_t)((warp_m * 64 + i * 16 + (lane & 15)) * SROW
                                              + s16 * 16 + ((lane >> 4) << 3)) * 2;
                ldsm4(ad, af[i][0], af[i][1], af[i][2], af[i][3]);
            }
            uint32_t bfr[8][2];
            #pragma unroll
            for (int p = 0; p < 4; p++) {
                uint32_t bd = sb + (uint32_t)((warp_n * 64 + p * 16 + (((lane >> 4) & 1) << 3)
                                               + (lane & 7)) * SROW
                                              + s16 * 16 + (((lane >> 3) & 1) << 3)) * 2;
                uint32_t r0, r1, r2, r3;
                ldsm4(bd, r0, r1, r2, r3);
                bfr[2 * p][0] = r0; bfr[2 * p][1] = r1;
                bfr[2 * p + 1][0] = r2; bfr[2 * p + 1][1] = r3;
            }
            #pragma unroll
            for (int i = 0; i < 4; i++)
                #pragma unroll
                for (int j = 0; j < 8; j++)
                    mma_bf16(acc[i][j][0], acc[i][j][1], acc[i][j][2], acc[i][j][3],
                             af[i][0], af[i][1], af[i][2], af[i][3],
                             bfr[j][0], bfr[j][1]);
        }
    }

    // ---- epilogue ----
    #pragma unroll
    for (int i = 0; i < 4; i++) {
        int rbase = m0 + warp_m * 64 + i * 16 + (lane >> 2);
        #pragma unroll
        for (int half = 0; half < 2; half++) {
            int row = rbase + half * 8;
            if (MODE == 5) {
                const float* gp = G + (size_t)row * N;
                __nv_bfloat16* orow = C3 + (size_t)row * (3 * N);
                #pragma unroll
                for (int j = 0; j < 8; j++) {
                    int c = n0 + warp_n * 64 + j * 8 + ((lane & 3) << 1);
                    float p0 = gp[c]     * acc[i][j][half * 2 + 0];
                    float p1 = gp[c + 1] * acc[i][j][half * 2 + 1];
                    __nv_bfloat16 h0 = __float2bfloat16_rn(p0);
                    __nv_bfloat16 h1 = __float2bfloat16_rn(p1);
                    uint32_t hh; { __nv_bfloat162 t; t.x = h0; t.y = h1; hh = *(uint32_t*)&t; }
                    uint32_t ll = pack_bf2(p0 - __bfloat162float(h0),
                                           p1 - __bfloat162float(h1));
                    *(uint32_t*)&orow[c]         = hh;
                    *(uint32_t*)&orow[N + c]     = ll;
                    *(uint32_t*)&orow[2 * N + c] = hh;
                }
            } else {
                float* cp = C + (size_t)row * N;
                #pragma unroll
                for (int j = 0; j < 8; j++) {
                    int c = n0 + warp_n * 64 + j * 8 + ((lane & 3) << 1);
                    float v0 = acc[i][j][half * 2 + 0];
                    float v1 = acc[i][j][half * 2 + 1];
                    if (MODE == 1) {
                        float2 o = *(float2*)(cp + c);
                        v0 += o.x; v1 += o.y;
                    } else if (MODE == 2) {
                        v0 = v0 / (1.f + __expf(-v0));
                        v1 = v1 / (1.f + __expf(-v1));
                    }
                    float2 w; w.x = v0; w.y = v1;
                    *(float2*)(cp + c) = w;
                }
            }
        }
    }
}

// ---------------- host launch ----------------
extern "C" void kernel_launch(void* const* d_in, const int* in_sizes, int n_in,
                              void* d_out, int out_size)
{
    const int*   ids    = (const int*)d_in[0];
    const float* cosb   = (const float*)d_in[2];
    const float* sinb   = (const float*)d_in[3];
    const float* embed  = (const float*)d_in[4];
    const float* q_w    = (const float*)d_in[5];
    const float* k_w    = (const float*)d_in[6];
    const float* v_w    = (const float*)d_in[7];
    const float* o_w    = (const float*)d_in[8];
    const float* qn     = (const float*)d_in[9];
    const float* kn     = (const float*)d_in[10];
    const float* ln1    = (const float*)d_in[11];
    const float* ln2    = (const float*)d_in[12];
    const float* gate_w = (const float*)d_in[13];
    const float* up_w   = (const float*)d_in[14];
    const float* down_w = (const float*)d_in[15];

    float* h = (float*)d_out;

    float *pqkv, *pgate;
    __nv_bfloat16 *px3, *pctx3, *pm3, *pwqkv, *pwo, *pwgate, *pwup, *pwdown;
    cudaGetSymbolAddress((void**)&pqkv, g_qkv);
    cudaGetSymbolAddress((void**)&pgate, g_gate);
    cudaGetSymbolAddress((void**)&px3, a3_x);
    cudaGetSymbolAddress((void**)&pctx3, a3_ctx);
    cudaGetSymbolAddress((void**)&pm3, a3_mlp);
    cudaGetSymbolAddress((void**)&pwqkv, w3_qkv);
    cudaGetSymbolAddress((void**)&pwo, w3_o);
    cudaGetSymbolAddress((void**)&pwgate, w3_gate);
    cudaGetSymbolAddress((void**)&pwup, w3_up);
    cudaGetSymbolAddress((void**)&pwdown, w3_down);

    cudaFuncSetAttribute(hgemm3_kernel<0>, cudaFuncAttributeMaxDynamicSharedMemorySize, GEMM_SMEM);
    cudaFuncSetAttribute(hgemm3_kernel<1>, cudaFuncAttributeMaxDynamicSharedMemorySize, GEMM_SMEM);
    cudaFuncSetAttribute(hgemm3_kernel<2>, cudaFuncAttributeMaxDynamicSharedMemorySize, GEMM_SMEM);
    cudaFuncSetAttribute(hgemm3_kernel<5>, cudaFuncAttributeMaxDynamicSharedMemorySize, GEMM_SMEM);

    // ---- weight conversion (every launch; deterministic) ----
    const int WB = 1184, WT = 256;
    for (int l = 0; l < N_LAYERS; l++) {
        __nv_bfloat16* wq = pwqkv + (size_t)l * QKV_N * K3_D;
        wconv_kernel<<<WB, WT>>>((const float2*)(q_w + (size_t)l * 2048 * D_MODEL),
                                 wq, 2048, D_MODEL);
        wconv_kernel<<<WB, WT>>>((const float2*)(k_w + (size_t)l * 1024 * D_MODEL),
                                 wq + (size_t)2048 * K3_D, 1024, D_MODEL);
        wconv_kernel<<<WB, WT>>>((const float2*)(v_w + (size_t)l * 1024 * D_MODEL),
                                 wq + (size_t)3072 * K3_D, 1024, D_MODEL);
        wconv_kernel<<<WB, WT>>>((const float2*)(o_w + (size_t)l * D_MODEL * 2048),
                                 pwo + (size_t)l * D_MODEL * K3_D, D_MODEL, 2048);
        wconv_kernel<<<WB, WT>>>((const float2*)(gate_w + (size_t)l * INTER * D_MODEL),
                                 pwgate + (size_t)l * INTER * K3_D, INTER, D_MODEL);
        wconv_kernel<<<WB, WT>>>((const float2*)(up_w + (size_t)l * INTER * D_MODEL),
                                 pwup + (size_t)l * INTER * K3_D, INTER, D_MODEL);
        wconv_kernel<<<WB, WT>>>((const float2*)(down_w + (size_t)l * D_MODEL * INTER),
                                 pwdown + (size_t)l * D_MODEL * K3_I, D_MODEL, INTER);
    }

    embed_kernel<<<S_LEN, 256>>>(ids, embed, h);

    for (int l = 0; l < N_LAYERS; l++) {
        __nv_bfloat16* wq = pwqkv + (size_t)l * QKV_N * K3_D;
        __nv_bfloat16* wo = pwo + (size_t)l * D_MODEL * K3_D;
        __nv_bfloat16* wg = pwgate + (size_t)l * INTER * K3_D;
        __nv_bfloat16* wu = pwup + (size_t)l * INTER * K3_D;
        __nv_bfloat16* wd = pwdown + (size_t)l * D_MODEL * K3_I;

        rmsnorm_t_kernel<<<S_LEN, 256>>>(h, ln1 + l * D_MODEL, px3);

        hgemm3_kernel<0><<<dim3(QKV_N / BN, S_LEN / BM), 256, GEMM_SMEM>>>(
            px3, wq, pqkv, nullptr, nullptr, S_LEN, QKV_N, K3_D);

        qknorm_rope_kernel<<<dim3(S_LEN, N_HEADS + N_KV), 128>>>(
            pqkv, qn + l * HEAD_DIM, kn + l * HEAD_DIM, cosb, sinb);

        attn_kernel<<<dim3(S_LEN / 32, N_HEADS), 128>>>(pqkv, pctx3);

        hgemm3_kernel<1><<<dim3(D_MODEL / BN, S_LEN / BM), 256, GEMM_SMEM>>>(
            pctx3, wo, h, nullptr, nullptr, S_LEN, D_MODEL, K3_D);

        rmsnorm_t_kernel<<<S_LEN, 256>>>(h, ln2 + l * D_MODEL, px3);

        hgemm3_kernel<2><<<dim3(INTER / BN, S_LEN / BM), 256, GEMM_SMEM>>>(
            px3, wg, pgate, nullptr, nullptr, S_LEN, INTER, K3_D);

        hgemm3_kernel<5><<<dim3(INTER / BN, S_LEN / BM), 256, GEMM_SMEM>>>(
            px3, wu, nullptr, pgate, pm3, S_LEN, INTER, K3_D);

        hgemm3_kernel<1><<<dim3(D_MODEL / BN, S_LEN / BM), 256, GEMM_SMEM>>>(
            pm3, wd, h, nullptr, nullptr, S_LEN, D_MODEL, K3_I);
    }
}

// round 7
// speedup vs baseline: 1.0226x; 1.0226x over previous
#include <cuda_runtime.h>
#include <cuda_bf16.h>
#include <math.h>
#include <stdint.h>

// ---------------- problem constants ----------------
#define S_LEN 2048
#define D_MODEL 2048
#define N_HEADS 16
#define N_KV 8
#define HEAD_DIM 128
#define INTER 6144
#define N_LAYERS 2
#define EPS 1e-6f
#define ATT_SCALE 0.08838834764831845f

#define K3_D (3 * D_MODEL)   // 6144
#define K3_I (3 * INTER)     // 18432
#define QKV_N 4096           // q(2048) + k(1024) + v(1024)

// ---------------- scratch (device globals, no allocs) ----------------
__device__ float g_qkv[S_LEN * QKV_N];
__device__ float g_gate[S_LEN * INTER];
__device__ __nv_bfloat16 a3_x[S_LEN * K3_D];
__device__ __nv_bfloat16 a3_ctx[S_LEN * K3_D];
__device__ __nv_bfloat16 a3_mlp[S_LEN * K3_I];

__device__ __nv_bfloat16 w3_qkv[N_LAYERS * QKV_N * K3_D];
__device__ __nv_bfloat16 w3_o[N_LAYERS * D_MODEL * K3_D];
__device__ __nv_bfloat16 w3_gate[N_LAYERS * INTER * K3_D];
__device__ __nv_bfloat16 w3_up[N_LAYERS * INTER * K3_D];
__device__ __nv_bfloat16 w3_down[N_LAYERS * D_MODEL * K3_I];

// ---------------- helpers ----------------
__device__ __forceinline__ uint32_t pack_bf2(float x, float y)
{
    __nv_bfloat162 v = __floats2bfloat162_rn(x, y);
    return *(uint32_t*)&v;
}

// ---------------- weight conversion: W[rows][K] fp32 -> [bh|bh|bl] bf16 ----------------
__global__ void wconv_kernel(const float2* __restrict__ src,
                             __nv_bfloat16* __restrict__ dst,
                             int rows, int K)
{
    int half = K >> 1;
    int total = rows * half;
    for (int i = blockIdx.x * blockDim.x + threadIdx.x; i < total;
         i += gridDim.x * blockDim.x) {
        int n = i / half, k2 = i - n * half;
        float2 v = src[(size_t)n * half + k2];
        __nv_bfloat16 h0 = __float2bfloat16_rn(v.x);
        __nv_bfloat16 h1 = __float2bfloat16_rn(v.y);
        float l0 = v.x - __bfloat162float(h0);
        float l1 = v.y - __bfloat162float(h1);
        uint32_t hh; { __nv_bfloat162 t; t.x = h0; t.y = h1; hh = *(uint32_t*)&t; }
        uint32_t ll = pack_bf2(l0, l1);
        __nv_bfloat16* row = dst + (size_t)n * (3 * K);
        *(uint32_t*)&row[2 * k2]         = hh;
        *(uint32_t*)&row[K + 2 * k2]     = hh;
        *(uint32_t*)&row[2 * K + 2 * k2] = ll;
    }
}

// ---------------- embedding gather ----------------
__global__ void embed_kernel(const int* __restrict__ ids,
                             const float* __restrict__ embed,
                             float* __restrict__ h)
{
    int s = blockIdx.x;
    int id = ids[s];
    const float4* src = (const float4*)(embed + (size_t)id * D_MODEL);
    float4* dst = (float4*)(h + (size_t)s * D_MODEL);
    for (int i = threadIdx.x; i < D_MODEL / 4; i += blockDim.x)
        dst[i] = src[i];
}

// ---------------- RMSNorm -> triple-bf16 [ah|al|ah] ----------------
__global__ void rmsnorm_t_kernel(const float* __restrict__ in,
                                 const float* __restrict__ sc,
                                 __nv_bfloat16* __restrict__ out3)
{
    int row = blockIdx.x;
    const float* p = in + (size_t)row * D_MODEL;
    float ss = 0.f;
    for (int d = threadIdx.x; d < D_MODEL; d += blockDim.x) {
        float v = p[d];
        ss = fmaf(v, v, ss);
    }
    #pragma unroll
    for (int o = 16; o > 0; o >>= 1) ss += __shfl_xor_sync(0xFFFFFFFFu, ss, o);
    __shared__ float red[8];
    int lane = threadIdx.x & 31, wid = threadIdx.x >> 5;
    if (lane == 0) red[wid] = ss;
    __syncthreads();
    float tot = 0.f;
    #pragma unroll
    for (int i = 0; i < 8; i++) tot += red[i];
    float r = rsqrtf(tot * (1.0f / D_MODEL) + EPS);
    __nv_bfloat16* orow = out3 + (size_t)row * K3_D;
    for (int d2 = threadIdx.x; d2 < D_MODEL / 2; d2 += blockDim.x) {
        int d = d2 * 2;
        float v0 = p[d] * r * sc[d];
        float v1 = p[d + 1] * r * sc[d + 1];
        __nv_bfloat16 h0 = __float2bfloat16_rn(v0);
        __nv_bfloat16 h1 = __float2bfloat16_rn(v1);
        uint32_t hh; { __nv_bfloat162 t; t.x = h0; t.y = h1; hh = *(uint32_t*)&t; }
        uint32_t ll = pack_bf2(v0 - __bfloat162float(h0), v1 - __bfloat162float(h1));
        *(uint32_t*)&orow[d]               = hh;
        *(uint32_t*)&orow[D_MODEL + d]     = ll;
        *(uint32_t*)&orow[2 * D_MODEL + d] = hh;
    }
}

// ---------------- per-head QK RMSNorm + RoPE (fused qkv buffer) ----------------
__global__ void qknorm_rope_kernel(float* __restrict__ qkv,
                                   const float* __restrict__ qn, const float* __restrict__ kn,
                                   const float* __restrict__ cosb, const float* __restrict__ sinb)
{
    int s = blockIdx.x;
    int head = blockIdx.y;
    float* vec;
    const float* sc;
    if (head < N_HEADS) {
        vec = qkv + (size_t)s * QKV_N + head * HEAD_DIM;
        sc = qn;
    } else {
        vec = qkv + (size_t)s * QKV_N + 2048 + (head - N_HEADS) * HEAD_DIM;
        sc = kn;
    }
    int d = threadIdx.x;
    float v = vec[d];
    float ss = v * v;
    #pragma unroll
    for (int o = 16; o > 0; o >>= 1) ss += __shfl_xor_sync(0xFFFFFFFFu, ss, o);
    __shared__ float red[4];
    int lane = d & 31, wid = d >> 5;
    if (lane == 0) red[wid] = ss;
    __syncthreads();
    float tot = red[0] + red[1] + red[2] + red[3];
    float nv = v * rsqrtf(tot * (1.0f / HEAD_DIM) + EPS) * sc[d];
    __shared__ float tmp[HEAD_DIM];
    tmp[d] = nv;
    __syncthreads();
    float rot = (d < 64) ? -tmp[d + 64] : tmp[d - 64];
    vec[d] = nv * cosb[(size_t)s * HEAD_DIM + d] + rot * sinb[(size_t)s * HEAD_DIM + d];
}

// ---------------- causal flash attention (fp32) -> triple-bf16 ctx ----------------
__global__ void __launch_bounds__(128) attn_kernel(
    const float* __restrict__ qkv, __nv_bfloat16* __restrict__ ctx3)
{
    __shared__ alignas(16) float q_sh[32][129];
    __shared__ alignas(16) float kvT[128][36];
    __shared__ alignas(16) float p_sh[32][33];
    __shared__ float m_sh[32], l_sh[32], al_sh[32];

    const int tid = threadIdx.x;
    const int qt = blockIdx.x, h = blockIdx.y;
    const int kvh = h >> 1;
    const int q0 = qt * 32;
    const int qr = tid & 31, grp = tid >> 5;
    const int d0 = grp * 32;

    const float* qb = qkv + h * HEAD_DIM;
    const float* kb = qkv + 2048 + kvh * HEAD_DIM;
    const float* vb = qkv + 3072 + kvh * HEAD_DIM;

    for (int i = tid; i < 32 * 128; i += 128) {
        int r = i >> 7, d = i & 127;
        q_sh[r][d] = qb[(size_t)(q0 + r) * QKV_N + d];
    }
    if (tid < 32) { m_sh[tid] = -1e30f; l_sh[tid] = 0.f; }
    float acc[32];
    #pragma unroll
    for (int j = 0; j < 32; j++) acc[j] = 0.f;

    const int nch = qt + 1;
    for (int c = 0; c < nch; c++) {
        const int k0 = c * 32;
        __syncthreads();
        for (int i = tid; i < 32 * 128; i += 128) {
            int r = i >> 7, d = i & 127;
            kvT[d][r] = kb[(size_t)(k0 + r) * QKV_N + d];
        }
        __syncthreads();
        float sc[8];
        #pragma unroll
        for (int jj = 0; jj < 8; jj++) sc[jj] = 0.f;
        for (int d = 0; d < 128; d++) {
            float qv = q_sh[qr][d];
            const float4 ka = *(const float4*)&kvT[d][grp * 8];
            const float4 kbv = *(const float4*)&kvT[d][grp * 8 + 4];
            sc[0] = fmaf(qv, ka.x, sc[0]);
            sc[1] = fmaf(qv, ka.y, sc[1]);
            sc[2] = fmaf(qv, ka.z, sc[2]);
            sc[3] = fmaf(qv, ka.w, sc[3]);
            sc[4] = fmaf(qv, kbv.x, sc[4]);
            sc[5] = fmaf(qv, kbv.y, sc[5]);
            sc[6] = fmaf(qv, kbv.z, sc[6]);
            sc[7] = fmaf(qv, kbv.w, sc[7]);
        }
        #pragma unroll
        for (int jj = 0; jj < 8; jj++) {
            int kk = grp * 8 + jj;
            float s = sc[jj] * ATT_SCALE;
            if (k0 + kk > q0 + qr) s = -1e30f;
            p_sh[qr][kk] = s;
        }
        __syncthreads();
        if (tid < 32) {
            float mold = m_sh[tid], m = mold;
            #pragma unroll
            for (int kk = 0; kk < 32; kk++) m = fmaxf(m, p_sh[tid][kk]);
            float alpha = __expf(mold - m);
            float rs = 0.f;
            #pragma unroll
            for (int kk = 0; kk < 32; kk++) {
                float p = __expf(p_sh[tid][kk] - m);
                p_sh[tid][kk] = p;
                rs += p;
            }
            m_sh[tid] = m;
            l_sh[tid] = l_sh[tid] * alpha + rs;
            al_sh[tid] = alpha;
        }
        __syncthreads();
        for (int i = tid; i < 32 * 128; i += 128) {
            int r = i >> 7, d = i & 127;
            kvT[d][r] = vb[(size_t)(k0 + r) * QKV_N + d];
        }
        __syncthreads();
        float pr[32];
        #pragma unroll
        for (int kk = 0; kk < 32; kk++) pr[kk] = p_sh[qr][kk];
        float alpha = al_sh[qr];
        #pragma unroll
        for (int j = 0; j < 32; j++) acc[j] *= alpha;
        #pragma unroll
        for (int j = 0; j < 32; j++) {
            const float* vrow = &kvT[d0 + j][0];
            float s0 = 0.f;
            #pragma unroll
            for (int kk = 0; kk < 32; kk++) s0 = fmaf(pr[kk], vrow[kk], s0);
            acc[j] += s0;
        }
    }
    __syncthreads();
    float inv = 1.0f / l_sh[qr];
    __nv_bfloat16* orow = ctx3 + (size_t)(q0 + qr) * K3_D + h * HEAD_DIM + d0;
    #pragma unroll
    for (int j = 0; j < 32; j += 2) {
        float v0 = acc[j] * inv;
        float v1 = acc[j + 1] * inv;
        __nv_bfloat16 h0 = __float2bfloat16_rn(v0);
        __nv_bfloat16 h1 = __float2bfloat16_rn(v1);
        uint32_t hh; { __nv_bfloat162 t; t.x = h0; t.y = h1; hh = *(uint32_t*)&t; }
        uint32_t ll = pack_bf2(v0 - __bfloat162float(h0), v1 - __bfloat162float(h1));
        *(uint32_t*)&orow[j]               = hh;
        *(uint32_t*)&orow[D_MODEL + j]     = ll;
        *(uint32_t*)&orow[2 * D_MODEL + j] = hh;
    }
}

// ============================================================
// bf16 GEMM (mma.sync): C[M,N] = A3[M,K3] @ B3[N,K3]^T
// Block 128x128, 256 threads (8 warps, 2M x 4N), warp tile 64x32.
// 3-stage cp.async pipeline, BK=64. __launch_bounds__(256,2) -> 2 CTAs/SM.
// MODE 0: C = acc ; 1: C += acc ; 2: C = silu(acc)
// MODE 5: C3 = triple_bf16(G * acc)
// ============================================================
#define BM 128
#define BN 128
#define BK 64
#define SROW 72             // halfs per smem row (64 + 8 pad)
#define GSTAGES 3
#define A_ST_HALFS (BM * SROW)
#define B_ST_HALFS (BN * SROW)
#define ST_HALFS (A_ST_HALFS + B_ST_HALFS)
#define GEMM_SMEM (GSTAGES * ST_HALFS * 2)   // 110592 bytes

__device__ __forceinline__ void mma_bf16(
    float& c0, float& c1, float& c2, float& c3,
    uint32_t a0, uint32_t a1, uint32_t a2, uint32_t a3,
    uint32_t b0, uint32_t b1)
{
    asm volatile(
        "mma.sync.aligned.m16n8k16.row.col.f32.bf16.bf16.f32 "
        "{%0,%1,%2,%3},{%4,%5,%6,%7},{%8,%9},{%0,%1,%2,%3};\n"
        : "+f"(c0), "+f"(c1), "+f"(c2), "+f"(c3)
        : "r"(a0), "r"(a1), "r"(a2), "r"(a3), "r"(b0), "r"(b1));
}

__device__ __forceinline__ void ldsm4(uint32_t addr, uint32_t& r0, uint32_t& r1,
                                      uint32_t& r2, uint32_t& r3)
{
    asm volatile("ldmatrix.sync.aligned.m8n8.x4.shared.b16 {%0,%1,%2,%3}, [%4];\n"
                 : "=r"(r0), "=r"(r1), "=r"(r2), "=r"(r3) : "r"(addr));
}

__device__ __forceinline__ uint32_t smem_u32(const void* p)
{
    uint32_t a;
    asm("{ .reg .u64 t; cvta.to.shared.u64 t, %1; cvt.u32.u64 %0, t; }"
        : "=r"(a) : "l"(p));
    return a;
}

__device__ __forceinline__ void cpasync16(uint32_t dst, const void* src)
{
    asm volatile("cp.async.cg.shared.global [%0], [%1], 16;\n"
                 :: "r"(dst), "l"(src) : "memory");
}

template <int MODE>
__global__ void __launch_bounds__(256, 2) hgemm3_kernel(
    const __nv_bfloat16* __restrict__ A3, const __nv_bfloat16* __restrict__ B3,
    float* __restrict__ C, const float* __restrict__ G,
    __nv_bfloat16* __restrict__ C3,
    int M, int N, int K3)
{
    extern __shared__ __align__(16) __nv_bfloat16 smem[];
    const int tid = threadIdx.x;
    const int lane = tid & 31;
    const int warp = tid >> 5;
    const int warp_m = warp & 1;   // 0..1 (64-row strips)
    const int warp_n = warp >> 1;  // 0..3 (32-col strips)
    const int m0 = blockIdx.y * BM;
    const int n0 = blockIdx.x * BN;
    const uint32_t sbase = smem_u32(smem);

    const __nv_bfloat16* Abase = A3 + (size_t)m0 * K3;
    const __nv_bfloat16* Bbase = B3 + (size_t)n0 * K3;
    const int nch = K3 >> 6;

    auto load_chunk = [&](int ch, int s) {
        uint32_t sa = sbase + (uint32_t)s * ST_HALFS * 2;
        uint32_t sb = sa + A_ST_HALFS * 2;
        const __nv_bfloat16* As = Abase + (size_t)ch * BK;
        const __nv_bfloat16* Bs = Bbase + (size_t)ch * BK;
        #pragma unroll
        for (int i = 0; i < 4; i++) {
            int u = tid + i * 256;
            int r = u >> 3, c8 = u & 7;
            cpasync16(sa + (uint32_t)(r * SROW + c8 * 8) * 2, As + (size_t)r * K3 + c8 * 8);
        }
        #pragma unroll
        for (int i = 0; i < 4; i++) {
            int u = tid + i * 256;
            int r = u >> 3, c8 = u & 7;
            cpasync16(sb + (uint32_t)(r * SROW + c8 * 8) * 2, Bs + (size_t)r * K3 + c8 * 8);
        }
        asm volatile("cp.async.commit_group;\n" ::: "memory");
    };

    float acc[4][4][4];
    #pragma unroll
    for (int i = 0; i < 4; i++)
        #pragma unroll
        for (int j = 0; j < 4; j++)
            #pragma unroll
            for (int r = 0; r < 4; r++) acc[i][j][r] = 0.f;

    load_chunk(0, 0);
    load_chunk(1, 1);

    int s = 0, s_next = 2;
    for (int ch = 0; ch < nch; ch++) {
        asm volatile("cp.async.wait_group 1;\n" ::: "memory");
        __syncthreads();
        if (ch + 2 < nch) {
            load_chunk(ch + 2, s_next);
        }

        uint32_t sa = sbase + (uint32_t)s * ST_HALFS * 2;
        uint32_t sb = sa + A_ST_HALFS * 2;
        #pragma unroll
        for (int s16 = 0; s16 < 4; s16++) {
            uint32_t af[4][4];
            #pragma unroll
            for (int i = 0; i < 4; i++) {
                uint32_t ad = sa + (uint32_t)((warp_m * 64 + i * 16 + (lane & 15)) * SROW
                                              + s16 * 16 + ((lane >> 4) << 3)) * 2;
                ldsm4(ad, af[i][0], af[i][1], af[i][2], af[i][3]);
            }
            uint32_t bfr[4][2];
            #pragma unroll
            for (int p = 0; p < 2; p++) {
                uint32_t bd = sb + (uint32_t)((warp_n * 32 + p * 16 + (((lane >> 4) & 1) << 3)
                                               + (lane & 7)) * SROW
                                              + s16 * 16 + (((lane >> 3) & 1) << 3)) * 2;
                uint32_t r0, r1, r2, r3;
                ldsm4(bd, r0, r1, r2, r3);
                bfr[2 * p][0] = r0; bfr[2 * p][1] = r1;
                bfr[2 * p + 1][0] = r2; bfr[2 * p + 1][1] = r3;
            }
            #pragma unroll
            for (int i = 0; i < 4; i++)
                #pragma unroll
                for (int j = 0; j < 4; j++)
                    mma_bf16(acc[i][j][0], acc[i][j][1], acc[i][j][2], acc[i][j][3],
                             af[i][0], af[i][1], af[i][2], af[i][3],
                             bfr[j][0], bfr[j][1]);
        }
        s = (s == 2) ? 0 : s + 1;
        s_next = (s_next == 2) ? 0 : s_next + 1;
    }

    // ---- epilogue ----
    #pragma unroll
    for (int i = 0; i < 4; i++) {
        int rbase = m0 + warp_m * 64 + i * 16 + (lane >> 2);
        #pragma unroll
        for (int half = 0; half < 2; half++) {
            int row = rbase + half * 8;
            if (MODE == 5) {
                const float* gp = G + (size_t)row * N;
                __nv_bfloat16* orow = C3 + (size_t)row * (3 * N);
                #pragma unroll
                for (int j = 0; j < 4; j++) {
                    int c = n0 + warp_n * 32 + j * 8 + ((lane & 3) << 1);
                    float p0 = gp[c]     * acc[i][j][half * 2 + 0];
                    float p1 = gp[c + 1] * acc[i][j][half * 2 + 1];
                    __nv_bfloat16 h0 = __float2bfloat16_rn(p0);
                    __nv_bfloat16 h1 = __float2bfloat16_rn(p1);
                    uint32_t hh; { __nv_bfloat162 t; t.x = h0; t.y = h1; hh = *(uint32_t*)&t; }
                    uint32_t ll = pack_bf2(p0 - __bfloat162float(h0),
                                           p1 - __bfloat162float(h1));
                    *(uint32_t*)&orow[c]         = hh;
                    *(uint32_t*)&orow[N + c]     = ll;
                    *(uint32_t*)&orow[2 * N + c] = hh;
                }
            } else {
                float* cp = C + (size_t)row * N;
                #pragma unroll
                for (int j = 0; j < 4; j++) {
                    int c = n0 + warp_n * 32 + j * 8 + ((lane & 3) << 1);
                    float v0 = acc[i][j][half * 2 + 0];
                    float v1 = acc[i][j][half * 2 + 1];
                    if (MODE == 1) {
                        float2 o = *(float2*)(cp + c);
                        v0 += o.x; v1 += o.y;
                    } else if (MODE == 2) {
                        v0 = v0 / (1.f + __expf(-v0));
                        v1 = v1 / (1.f + __expf(-v1));
                    }
                    float2 w; w.x = v0; w.y = v1;
                    *(float2*)(cp + c) = w;
                }
            }
        }
    }
}

// ---------------- host launch ----------------
extern "C" void kernel_launch(void* const* d_in, const int* in_sizes, int n_in,
                              void* d_out, int out_size)
{
    const int*   ids    = (const int*)d_in[0];
    const float* cosb   = (const float*)d_in[2];
    const float* sinb   = (const float*)d_in[3];
    const float* embed  = (const float*)d_in[4];
    const float* q_w    = (const float*)d_in[5];
    const float* k_w    = (const float*)d_in[6];
    const float* v_w    = (const float*)d_in[7];
    const float* o_w    = (const float*)d_in[8];
    const float* qn     = (const float*)d_in[9];
    const float* kn     = (const float*)d_in[10];
    const float* ln1    = (const float*)d_in[11];
    const float* ln2    = (const float*)d_in[12];
    const float* gate_w = (const float*)d_in[13];
    const float* up_w   = (const float*)d_in[14];
    const float* down_w = (const float*)d_in[15];

    float* h = (float*)d_out;

    float *pqkv, *pgate;
    __nv_bfloat16 *px3, *pctx3, *pm3, *pwqkv, *pwo, *pwgate, *pwup, *pwdown;
    cudaGetSymbolAddress((void**)&pqkv, g_qkv);
    cudaGetSymbolAddress((void**)&pgate, g_gate);
    cudaGetSymbolAddress((void**)&px3, a3_x);
    cudaGetSymbolAddress((void**)&pctx3, a3_ctx);
    cudaGetSymbolAddress((void**)&pm3, a3_mlp);
    cudaGetSymbolAddress((void**)&pwqkv, w3_qkv);
    cudaGetSymbolAddress((void**)&pwo, w3_o);
    cudaGetSymbolAddress((void**)&pwgate, w3_gate);
    cudaGetSymbolAddress((void**)&pwup, w3_up);
    cudaGetSymbolAddress((void**)&pwdown, w3_down);

    cudaFuncSetAttribute(hgemm3_kernel<0>, cudaFuncAttributeMaxDynamicSharedMemorySize, GEMM_SMEM);
    cudaFuncSetAttribute(hgemm3_kernel<1>, cudaFuncAttributeMaxDynamicSharedMemorySize, GEMM_SMEM);
    cudaFuncSetAttribute(hgemm3_kernel<2>, cudaFuncAttributeMaxDynamicSharedMemorySize, GEMM_SMEM);
    cudaFuncSetAttribute(hgemm3_kernel<5>, cudaFuncAttributeMaxDynamicSharedMemorySize, GEMM_SMEM);

    const int WB = 1184, WT = 256;

    // launches 1-3: layer-0 q/k/v weight conversion (so launch #6 = QKV hgemm for ncu)
    {
        __nv_bfloat16* wq = pwqkv;
        wconv_kernel<<<WB, WT>>>((const float2*)q_w, wq, 2048, D_MODEL);
        wconv_kernel<<<WB, WT>>>((const float2*)k_w, wq + (size_t)2048 * K3_D, 1024, D_MODEL);
        wconv_kernel<<<WB, WT>>>((const float2*)v_w, wq + (size_t)3072 * K3_D, 1024, D_MODEL);
    }

    embed_kernel<<<S_LEN, 256>>>(ids, embed, h);   // launch 4

    for (int l = 0; l < N_LAYERS; l++) {
        __nv_bfloat16* wq = pwqkv + (size_t)l * QKV_N * K3_D;
        __nv_bfloat16* wo = pwo + (size_t)l * D_MODEL * K3_D;
        __nv_bfloat16* wg = pwgate + (size_t)l * INTER * K3_D;
        __nv_bfloat16* wu = pwup + (size_t)l * INTER * K3_D;
        __nv_bfloat16* wd = pwdown + (size_t)l * D_MODEL * K3_I;

        if (l > 0) {
            wconv_kernel<<<WB, WT>>>((const float2*)(q_w + (size_t)l * 2048 * D_MODEL),
                                     wq, 2048, D_MODEL);
            wconv_kernel<<<WB, WT>>>((const float2*)(k_w + (size_t)l * 1024 * D_MODEL),
                                     wq + (size_t)2048 * K3_D, 1024, D_MODEL);
            wconv_kernel<<<WB, WT>>>((const float2*)(v_w + (size_t)l * 1024 * D_MODEL),
                                     wq + (size_t)3072 * K3_D, 1024, D_MODEL);
        }

        rmsnorm_t_kernel<<<S_LEN, 256>>>(h, ln1 + l * D_MODEL, px3);   // launch 5 (l=0)

        hgemm3_kernel<0><<<dim3(QKV_N / BN, S_LEN / BM), 256, GEMM_SMEM>>>(
            px3, wq, pqkv, nullptr, nullptr, S_LEN, QKV_N, K3_D);      // launch 6 (l=0)

        qknorm_rope_kernel<<<dim3(S_LEN, N_HEADS + N_KV), 128>>>(
            pqkv, qn + l * HEAD_DIM, kn + l * HEAD_DIM, cosb, sinb);

        attn_kernel<<<dim3(S_LEN / 32, N_HEADS), 128>>>(pqkv, pctx3);

        wconv_kernel<<<WB, WT>>>((const float2*)(o_w + (size_t)l * D_MODEL * 2048),
                                 wo, D_MODEL, 2048);

        hgemm3_kernel<1><<<dim3(D_MODEL / BN, S_LEN / BM), 256, GEMM_SMEM>>>(
            pctx3, wo, h, nullptr, nullptr, S_LEN, D_MODEL, K3_D);

        rmsnorm_t_kernel<<<S_LEN, 256>>>(h, ln2 + l * D_MODEL, px3);

        wconv_kernel<<<WB, WT>>>((const float2*)(gate_w + (size_t)l * INTER * D_MODEL),
                                 wg, INTER, D_MODEL);

        hgemm3_kernel<2><<<dim3(INTER / BN, S_LEN / BM), 256, GEMM_SMEM>>>(
            px3, wg, pgate, nullptr, nullptr, S_LEN, INTER, K3_D);

        wconv_kernel<<<WB, WT>>>((const float2*)(up_w + (size_t)l * INTER * D_MODEL),
                                 wu, INTER, D_MODEL);

        hgemm3_kernel<5><<<dim3(INTER / BN, S_LEN / BM), 256, GEMM_SMEM>>>(
            px3, wu, nullptr, pgate, pm3, S_LEN, INTER, K3_D);

        wconv_kernel<<<WB, WT>>>((const float2*)(down_w + (size_t)l * D_MODEL * INTER),
                                 wd, D_MODEL, INTER);

        hgemm3_kernel<1><<<dim3(D_MODEL / BN, S_LEN / BM), 256, GEMM_SMEM>>>(
            pm3, wd, h, nullptr, nullptr, S_LEN, D_MODEL, K3_I);
    }
}

// round 8
// speedup vs baseline: 1.0520x; 1.0287x over previous
#include <cuda_runtime.h>
#include <cuda_bf16.h>
#include <math.h>
#include <stdint.h>

// ---------------- problem constants ----------------
#define S_LEN 2048
#define D_MODEL 2048
#define N_HEADS 16
#define N_KV 8
#define HEAD_DIM 128
#define INTER 6144
#define N_LAYERS 2
#define EPS 1e-6f
#define ATT_SCALE 0.08838834764831845f

#define K3_D (3 * D_MODEL)   // 6144
#define K3_I (3 * INTER)     // 18432
#define QKV_N 4096           // q(2048) + k(1024) + v(1024)
#define GU_N (2 * INTER)     // 12288 fused gate|up

// ---------------- scratch (device globals, no allocs) ----------------
__device__ float g_qkv[S_LEN * QKV_N];
__device__ float g_gu[S_LEN * GU_N];              // fused gate|up fp32 output
__device__ __nv_bfloat16 a3_x[S_LEN * K3_D];
__device__ __nv_bfloat16 a3_ctx[S_LEN * K3_D];
__device__ __nv_bfloat16 a3_mlp[S_LEN * K3_I];

__device__ __nv_bfloat16 w3_qkv[N_LAYERS * QKV_N * K3_D];
__device__ __nv_bfloat16 w3_o[N_LAYERS * D_MODEL * K3_D];
__device__ __nv_bfloat16 w3_gu[N_LAYERS * GU_N * K3_D];
__device__ __nv_bfloat16 w3_down[N_LAYERS * D_MODEL * K3_I];

// ---------------- helpers ----------------
__device__ __forceinline__ uint32_t pack_bf2(float x, float y)
{
    __nv_bfloat162 v = __floats2bfloat162_rn(x, y);
    return *(uint32_t*)&v;
}

__device__ __forceinline__ void triple_write(__nv_bfloat16* row, int K, int c,
                                             float v0, float v1)
{
    __nv_bfloat16 h0 = __float2bfloat16_rn(v0);
    __nv_bfloat16 h1 = __float2bfloat16_rn(v1);
    uint32_t hh; { __nv_bfloat162 t; t.x = h0; t.y = h1; hh = *(uint32_t*)&t; }
    uint32_t ll = pack_bf2(v0 - __bfloat162float(h0), v1 - __bfloat162float(h1));
    *(uint32_t*)&row[c]         = hh;
    *(uint32_t*)&row[K + c]     = ll;
    *(uint32_t*)&row[2 * K + c] = hh;
}

// ---------------- weight conversion: W[rows][K] fp32 -> [bh|bh|bl] bf16 ----------------
__global__ void wconv_kernel(const float2* __restrict__ src,
                             __nv_bfloat16* __restrict__ dst,
                             int rows, int K)
{
    int half = K >> 1;
    int total = rows * half;
    for (int i = blockIdx.x * blockDim.x + threadIdx.x; i < total;
         i += gridDim.x * blockDim.x) {
        int n = i / half, k2 = i - n * half;
        float2 v = src[(size_t)n * half + k2];
        __nv_bfloat16 h0 = __float2bfloat16_rn(v.x);
        __nv_bfloat16 h1 = __float2bfloat16_rn(v.y);
        float l0 = v.x - __bfloat162float(h0);
        float l1 = v.y - __bfloat162float(h1);
        uint32_t hh; { __nv_bfloat162 t; t.x = h0; t.y = h1; hh = *(uint32_t*)&t; }
        uint32_t ll = pack_bf2(l0, l1);
        __nv_bfloat16* row = dst + (size_t)n * (3 * K);
        *(uint32_t*)&row[2 * k2]         = hh;
        *(uint32_t*)&row[K + 2 * k2]     = hh;
        *(uint32_t*)&row[2 * K + 2 * k2] = ll;
    }
}

// merged q/k/v weight conversion (single launch)
__global__ void wconv_qkv_kernel(const float2* __restrict__ q,
                                 const float2* __restrict__ k,
                                 const float2* __restrict__ v,
                                 __nv_bfloat16* __restrict__ dst)
{
    const int half = D_MODEL >> 1;
    const int total = QKV_N * half;
    for (int i = blockIdx.x * blockDim.x + threadIdx.x; i < total;
         i += gridDim.x * blockDim.x) {
        int n = i / half, k2 = i - n * half;
        const float2* src = (n < 2048) ? q + (size_t)n * half
                          : (n < 3072) ? k + (size_t)(n - 2048) * half
                                       : v + (size_t)(n - 3072) * half;
        float2 val = src[k2];
        __nv_bfloat16 h0 = __float2bfloat16_rn(val.x);
        __nv_bfloat16 h1 = __float2bfloat16_rn(val.y);
        uint32_t hh; { __nv_bfloat162 t; t.x = h0; t.y = h1; hh = *(uint32_t*)&t; }
        uint32_t ll = pack_bf2(val.x - __bfloat162float(h0),
                               val.y - __bfloat162float(h1));
        __nv_bfloat16* row = dst + (size_t)n * K3_D;
        *(uint32_t*)&row[2 * k2]               = hh;
        *(uint32_t*)&row[D_MODEL + 2 * k2]     = hh;
        *(uint32_t*)&row[2 * D_MODEL + 2 * k2] = ll;
    }
}

// ---------------- embedding gather ----------------
__global__ void embed_kernel(const int* __restrict__ ids,
                             const float* __restrict__ embed,
                             float* __restrict__ h)
{
    int s = blockIdx.x;
    int id = ids[s];
    const float4* src = (const float4*)(embed + (size_t)id * D_MODEL);
    float4* dst = (float4*)(h + (size_t)s * D_MODEL);
    for (int i = threadIdx.x; i < D_MODEL / 4; i += blockDim.x)
        dst[i] = src[i];
}

// ---------------- RMSNorm -> triple-bf16 [ah|al|ah] ----------------
__global__ void rmsnorm_t_kernel(const float* __restrict__ in,
                                 const float* __restrict__ sc,
                                 __nv_bfloat16* __restrict__ out3)
{
    int row = blockIdx.x;
    const float* p = in + (size_t)row * D_MODEL;
    float ss = 0.f;
    for (int d = threadIdx.x; d < D_MODEL; d += blockDim.x) {
        float v = p[d];
        ss = fmaf(v, v, ss);
    }
    #pragma unroll
    for (int o = 16; o > 0; o >>= 1) ss += __shfl_xor_sync(0xFFFFFFFFu, ss, o);
    __shared__ float red[8];
    int lane = threadIdx.x & 31, wid = threadIdx.x >> 5;
    if (lane == 0) red[wid] = ss;
    __syncthreads();
    float tot = 0.f;
    #pragma unroll
    for (int i = 0; i < 8; i++) tot += red[i];
    float r = rsqrtf(tot * (1.0f / D_MODEL) + EPS);
    __nv_bfloat16* orow = out3 + (size_t)row * K3_D;
    for (int d2 = threadIdx.x; d2 < D_MODEL / 2; d2 += blockDim.x) {
        int d = d2 * 2;
        triple_write(orow, D_MODEL, d, p[d] * r * sc[d], p[d + 1] * r * sc[d + 1]);
    }
}

// ---------------- silu(gate)*up -> triple-bf16 ----------------
__global__ void silumul_t_kernel(const float* __restrict__ gu,
                                 __nv_bfloat16* __restrict__ out3)
{
    int row = blockIdx.x;
    const float* g = gu + (size_t)row * GU_N;
    const float* u = g + INTER;
    __nv_bfloat16* orow = out3 + (size_t)row * K3_I;
    for (int d2 = threadIdx.x; d2 < INTER / 2; d2 += blockDim.x) {
        int d = d2 * 2;
        float g0 = g[d], g1 = g[d + 1];
        float v0 = g0 / (1.f + __expf(-g0)) * u[d];
        float v1 = g1 / (1.f + __expf(-g1)) * u[d + 1];
        triple_write(orow, INTER, d, v0, v1);
    }
}

// ---------------- per-head QK RMSNorm + RoPE (fused qkv buffer) ----------------
__global__ void qknorm_rope_kernel(float* __restrict__ qkv,
                                   const float* __restrict__ qn, const float* __restrict__ kn,
                                   const float* __restrict__ cosb, const float* __restrict__ sinb)
{
    int s = blockIdx.x;
    int head = blockIdx.y;
    float* vec;
    const float* sc;
    if (head < N_HEADS) {
        vec = qkv + (size_t)s * QKV_N + head * HEAD_DIM;
        sc = qn;
    } else {
        vec = qkv + (size_t)s * QKV_N + 2048 + (head - N_HEADS) * HEAD_DIM;
        sc = kn;
    }
    int d = threadIdx.x;
    float v = vec[d];
    float ss = v * v;
    #pragma unroll
    for (int o = 16; o > 0; o >>= 1) ss += __shfl_xor_sync(0xFFFFFFFFu, ss, o);
    __shared__ float red[4];
    int lane = d & 31, wid = d >> 5;
    if (lane == 0) red[wid] = ss;
    __syncthreads();
    float tot = red[0] + red[1] + red[2] + red[3];
    float nv = v * rsqrtf(tot * (1.0f / HEAD_DIM) + EPS) * sc[d];
    __shared__ float tmp[HEAD_DIM];
    tmp[d] = nv;
    __syncthreads();
    float rot = (d < 64) ? -tmp[d + 64] : tmp[d - 64];
    vec[d] = nv * cosb[(size_t)s * HEAD_DIM + d] + rot * sinb[(size_t)s * HEAD_DIM + d];
}

// ---------------- causal flash attention (fp32) -> triple-bf16 ctx ----------------
__global__ void __launch_bounds__(128) attn_kernel(
    const float* __restrict__ qkv, __nv_bfloat16* __restrict__ ctx3)
{
    __shared__ alignas(16) float q_sh[32][129];
    __shared__ alignas(16) float kvT[128][36];
    __shared__ alignas(16) float p_sh[32][33];
    __shared__ float m_sh[32], l_sh[32], al_sh[32];

    const int tid = threadIdx.x;
    const int qt = blockIdx.x, h = blockIdx.y;
    const int kvh = h >> 1;
    const int q0 = qt * 32;
    const int qr = tid & 31, grp = tid >> 5;
    const int d0 = grp * 32;

    const float* qb = qkv + h * HEAD_DIM;
    const float* kb = qkv + 2048 + kvh * HEAD_DIM;
    const float* vb = qkv + 3072 + kvh * HEAD_DIM;

    for (int i = tid; i < 32 * 128; i += 128) {
        int r = i >> 7, d = i & 127;
        q_sh[r][d] = qb[(size_t)(q0 + r) * QKV_N + d];
    }
    if (tid < 32) { m_sh[tid] = -1e30f; l_sh[tid] = 0.f; }
    float acc[32];
    #pragma unroll
    for (int j = 0; j < 32; j++) acc[j] = 0.f;

    const int nch = qt + 1;
    for (int c = 0; c < nch; c++) {
        const int k0 = c * 32;
        __syncthreads();
        for (int i = tid; i < 32 * 128; i += 128) {
            int r = i >> 7, d = i & 127;
            kvT[d][r] = kb[(size_t)(k0 + r) * QKV_N + d];
        }
        __syncthreads();
        float sc[8];
        #pragma unroll
        for (int jj = 0; jj < 8; jj++) sc[jj] = 0.f;
        for (int d = 0; d < 128; d++) {
            float qv = q_sh[qr][d];
            const float4 ka = *(const float4*)&kvT[d][grp * 8];
            const float4 kbv = *(const float4*)&kvT[d][grp * 8 + 4];
            sc[0] = fmaf(qv, ka.x, sc[0]);
            sc[1] = fmaf(qv, ka.y, sc[1]);
            sc[2] = fmaf(qv, ka.z, sc[2]);
            sc[3] = fmaf(qv, ka.w, sc[3]);
            sc[4] = fmaf(qv, kbv.x, sc[4]);
            sc[5] = fmaf(qv, kbv.y, sc[5]);
            sc[6] = fmaf(qv, kbv.z, sc[6]);
            sc[7] = fmaf(qv, kbv.w, sc[7]);
        }
        #pragma unroll
        for (int jj = 0; jj < 8; jj++) {
            int kk = grp * 8 + jj;
            float s = sc[jj] * ATT_SCALE;
            if (k0 + kk > q0 + qr) s = -1e30f;
            p_sh[qr][kk] = s;
        }
        __syncthreads();
        if (tid < 32) {
            float mold = m_sh[tid], m = mold;
            #pragma unroll
            for (int kk = 0; kk < 32; kk++) m = fmaxf(m, p_sh[tid][kk]);
            float alpha = __expf(mold - m);
            float rs = 0.f;
            #pragma unroll
            for (int kk = 0; kk < 32; kk++) {
                float p = __expf(p_sh[tid][kk] - m);
                p_sh[tid][kk] = p;
                rs += p;
            }
            m_sh[tid] = m;
            l_sh[tid] = l_sh[tid] * alpha + rs;
            al_sh[tid] = alpha;
        }
        __syncthreads();
        for (int i = tid; i < 32 * 128; i += 128) {
            int r = i >> 7, d = i & 127;
            kvT[d][r] = vb[(size_t)(k0 + r) * QKV_N + d];
        }
        __syncthreads();
        float pr[32];
        #pragma unroll
        for (int kk = 0; kk < 32; kk++) pr[kk] = p_sh[qr][kk];
        float alpha = al_sh[qr];
        #pragma unroll
        for (int j = 0; j < 32; j++) acc[j] *= alpha;
        #pragma unroll
        for (int j = 0; j < 32; j++) {
            const float4* vr = (const float4*)&kvT[d0 + j][0];  // 16B-aligned (36 floats/row)
            float s0 = 0.f;
            #pragma unroll
            for (int q4 = 0; q4 < 8; q4++) {
                float4 v4 = vr[q4];
                s0 = fmaf(pr[4 * q4 + 0], v4.x, s0);
                s0 = fmaf(pr[4 * q4 + 1], v4.y, s0);
                s0 = fmaf(pr[4 * q4 + 2], v4.z, s0);
                s0 = fmaf(pr[4 * q4 + 3], v4.w, s0);
            }
            acc[j] += s0;
        }
    }
    __syncthreads();
    float inv = 1.0f / l_sh[qr];
    __nv_bfloat16* orow = ctx3 + (size_t)(q0 + qr) * K3_D + h * HEAD_DIM + d0;
    #pragma unroll
    for (int j = 0; j < 32; j += 2)
        triple_write(orow - (h * HEAD_DIM + d0) + 0, D_MODEL, h * HEAD_DIM + d0 + j,
                     acc[j] * inv, acc[j + 1] * inv);
}

// ============================================================
// bf16 GEMM (mma.sync): C[M,N] = A3[M,K3] @ B3[N,K3]^T
// Block 128x128, 256 threads (8 warps, 2M x 4N), warp tile 64x32.
// 3-stage cp.async pipeline, BK=64. __launch_bounds__(256,2) -> 2 CTAs/SM.
// MODE 0: C = acc ; 1: C += acc
// ============================================================
#define BM 128
#define BN 128
#define BK 64
#define SROW 72
#define GSTAGES 3
#define A_ST_HALFS (BM * SROW)
#define B_ST_HALFS (BN * SROW)
#define ST_HALFS (A_ST_HALFS + B_ST_HALFS)
#define GEMM_SMEM (GSTAGES * ST_HALFS * 2)

__device__ __forceinline__ void mma_bf16(
    float& c0, float& c1, float& c2, float& c3,
    uint32_t a0, uint32_t a1, uint32_t a2, uint32_t a3,
    uint32_t b0, uint32_t b1)
{
    asm volatile(
        "mma.sync.aligned.m16n8k16.row.col.f32.bf16.bf16.f32 "
        "{%0,%1,%2,%3},{%4,%5,%6,%7},{%8,%9},{%0,%1,%2,%3};\n"
        : "+f"(c0), "+f"(c1), "+f"(c2), "+f"(c3)
        : "r"(a0), "r"(a1), "r"(a2), "r"(a3), "r"(b0), "r"(b1));
}

__device__ __forceinline__ void ldsm4(uint32_t addr, uint32_t& r0, uint32_t& r1,
                                      uint32_t& r2, uint32_t& r3)
{
    asm volatile("ldmatrix.sync.aligned.m8n8.x4.shared.b16 {%0,%1,%2,%3}, [%4];\n"
                 : "=r"(r0), "=r"(r1), "=r"(r2), "=r"(r3) : "r"(addr));
}

__device__ __forceinline__ uint32_t smem_u32(const void* p)
{
    uint32_t a;
    asm("{ .reg .u64 t; cvta.to.shared.u64 t, %1; cvt.u32.u64 %0, t; }"
        : "=r"(a) : "l"(p));
    return a;
}

__device__ __forceinline__ void cpasync16(uint32_t dst, const void* src)
{
    asm volatile("cp.async.cg.shared.global [%0], [%1], 16;\n"
                 :: "r"(dst), "l"(src) : "memory");
}

template <int MODE>
__global__ void __launch_bounds__(256, 2) hgemm3_kernel(
    const __nv_bfloat16* __restrict__ A3, const __nv_bfloat16* __restrict__ B3,
    float* __restrict__ C, int M, int N, int K3)
{
    extern __shared__ __align__(16) __nv_bfloat16 smem[];
    const int tid = threadIdx.x;
    const int lane = tid & 31;
    const int warp = tid >> 5;
    const int warp_m = warp & 1;
    const int warp_n = warp >> 1;
    const int m0 = blockIdx.y * BM;
    const int n0 = blockIdx.x * BN;
    const uint32_t sbase = smem_u32(smem);

    const __nv_bfloat16* Abase = A3 + (size_t)m0 * K3;
    const __nv_bfloat16* Bbase = B3 + (size_t)n0 * K3;
    const int nch = K3 >> 6;

    auto load_chunk = [&](int ch, int s) {
        uint32_t sa = sbase + (uint32_t)s * ST_HALFS * 2;
        uint32_t sb = sa + A_ST_HALFS * 2;
        const __nv_bfloat16* As = Abase + (size_t)ch * BK;
        const __nv_bfloat16* Bs = Bbase + (size_t)ch * BK;
        #pragma unroll
        for (int i = 0; i < 4; i++) {
            int u = tid + i * 256;
            int r = u >> 3, c8 = u & 7;
            cpasync16(sa + (uint32_t)(r * SROW + c8 * 8) * 2, As + (size_t)r * K3 + c8 * 8);
        }
        #pragma unroll
        for (int i = 0; i < 4; i++) {
            int u = tid + i * 256;
            int r = u >> 3, c8 = u & 7;
            cpasync16(sb + (uint32_t)(r * SROW + c8 * 8) * 2, Bs + (size_t)r * K3 + c8 * 8);
        }
        asm volatile("cp.async.commit_group;\n" ::: "memory");
    };

    float acc[4][4][4];
    #pragma unroll
    for (int i = 0; i < 4; i++)
        #pragma unroll
        for (int j = 0; j < 4; j++)
            #pragma unroll
            for (int r = 0; r < 4; r++) acc[i][j][r] = 0.f;

    load_chunk(0, 0);
    load_chunk(1, 1);

    int s = 0, s_next = 2;
    for (int ch = 0; ch < nch; ch++) {
        asm volatile("cp.async.wait_group 1;\n" ::: "memory");
        __syncthreads();
        if (ch + 2 < nch) {
            load_chunk(ch + 2, s_next);
        }

        uint32_t sa = sbase + (uint32_t)s * ST_HALFS * 2;
        uint32_t sb = sa + A_ST_HALFS * 2;
        #pragma unroll
        for (int s16 = 0; s16 < 4; s16++) {
            uint32_t af[4][4];
            #pragma unroll
            for (int i = 0; i < 4; i++) {
                uint32_t ad = sa + (uint32_t)((warp_m * 64 + i * 16 + (lane & 15)) * SROW
                                              + s16 * 16 + ((lane >> 4) << 3)) * 2;
                ldsm4(ad, af[i][0], af[i][1], af[i][2], af[i][3]);
            }
            uint32_t bfr[4][2];
            #pragma unroll
            for (int p = 0; p < 2; p++) {
                uint32_t bd = sb + (uint32_t)((warp_n * 32 + p * 16 + (((lane >> 4) & 1) << 3)
                                               + (lane & 7)) * SROW
                                              + s16 * 16 + (((lane >> 3) & 1) << 3)) * 2;
                uint32_t r0, r1, r2, r3;
                ldsm4(bd, r0, r1, r2, r3);
                bfr[2 * p][0] = r0; bfr[2 * p][1] = r1;
                bfr[2 * p + 1][0] = r2; bfr[2 * p + 1][1] = r3;
            }
            #pragma unroll
            for (int i = 0; i < 4; i++)
                #pragma unroll
                for (int j = 0; j < 4; j++)
                    mma_bf16(acc[i][j][0], acc[i][j][1], acc[i][j][2], acc[i][j][3],
                             af[i][0], af[i][1], af[i][2], af[i][3],
                             bfr[j][0], bfr[j][1]);
        }
        s = (s == 2) ? 0 : s + 1;
        s_next = (s_next == 2) ? 0 : s_next + 1;
    }

    // ---- epilogue ----
    #pragma unroll
    for (int i = 0; i < 4; i++) {
        int rbase = m0 + warp_m * 64 + i * 16 + (lane >> 2);
        #pragma unroll
        for (int half = 0; half < 2; half++) {
            int row = rbase + half * 8;
            float* cp = C + (size_t)row * N;
            #pragma unroll
            for (int j = 0; j < 4; j++) {
                int c = n0 + warp_n * 32 + j * 8 + ((lane & 3) << 1);
                float v0 = acc[i][j][half * 2 + 0];
                float v1 = acc[i][j][half * 2 + 1];
                if (MODE == 1) {
                    float2 o = *(float2*)(cp + c);
                    v0 += o.x; v1 += o.y;
                }
                float2 w; w.x = v0; w.y = v1;
                *(float2*)(cp + c) = w;
            }
        }
    }
}

// ---------------- host launch ----------------
extern "C" void kernel_launch(void* const* d_in, const int* in_sizes, int n_in,
                              void* d_out, int out_size)
{
    const int*   ids    = (const int*)d_in[0];
    const float* cosb   = (const float*)d_in[2];
    const float* sinb   = (const float*)d_in[3];
    const float* embed  = (const float*)d_in[4];
    const float* q_w    = (const float*)d_in[5];
    const float* k_w    = (const float*)d_in[6];
    const float* v_w    = (const float*)d_in[7];
    const float* o_w    = (const float*)d_in[8];
    const float* qn     = (const float*)d_in[9];
    const float* kn     = (const float*)d_in[10];
    const float* ln1    = (const float*)d_in[11];
    const float* ln2    = (const float*)d_in[12];
    const float* gate_w = (const float*)d_in[13];
    const float* up_w   = (const float*)d_in[14];
    const float* down_w = (const float*)d_in[15];

    float* h = (float*)d_out;

    float *pqkv, *pgu;
    __nv_bfloat16 *px3, *pctx3, *pm3, *pwqkv, *pwo, *pwgu, *pwdown;
    cudaGetSymbolAddress((void**)&pqkv, g_qkv);
    cudaGetSymbolAddress((void**)&pgu, g_gu);
    cudaGetSymbolAddress((void**)&px3, a3_x);
    cudaGetSymbolAddress((void**)&pctx3, a3_ctx);
    cudaGetSymbolAddress((void**)&pm3, a3_mlp);
    cudaGetSymbolAddress((void**)&pwqkv, w3_qkv);
    cudaGetSymbolAddress((void**)&pwo, w3_o);
    cudaGetSymbolAddress((void**)&pwgu, w3_gu);
    cudaGetSymbolAddress((void**)&pwdown, w3_down);

    cudaFuncSetAttribute(hgemm3_kernel<0>, cudaFuncAttributeMaxDynamicSharedMemorySize, GEMM_SMEM);
    cudaFuncSetAttribute(hgemm3_kernel<1>, cudaFuncAttributeMaxDynamicSharedMemorySize, GEMM_SMEM);

    const int WB = 1184, WT = 256;

    embed_kernel<<<S_LEN, 256>>>(ids, embed, h);                 // #1

    for (int l = 0; l < N_LAYERS; l++) {
        __nv_bfloat16* wq = pwqkv + (size_t)l * QKV_N * K3_D;
        __nv_bfloat16* wo = pwo + (size_t)l * D_MODEL * K3_D;
        __nv_bfloat16* wg = pwgu + (size_t)l * GU_N * K3_D;
        __nv_bfloat16* wd = pwdown + (size_t)l * D_MODEL * K3_I;

        wconv_qkv_kernel<<<2048, 256>>>(                         // #2 (l=0)
            (const float2*)(q_w + (size_t)l * 2048 * D_MODEL),
            (const float2*)(k_w + (size_t)l * 1024 * D_MODEL),
            (const float2*)(v_w + (size_t)l * 1024 * D_MODEL), wq);

        rmsnorm_t_kernel<<<S_LEN, 256>>>(h, ln1 + l * D_MODEL, px3);   // #3 (l=0)

        hgemm3_kernel<0><<<dim3(QKV_N / BN, S_LEN / BM), 256, GEMM_SMEM>>>(
            px3, wq, pqkv, S_LEN, QKV_N, K3_D);                  // #4 (l=0) <- ncu target

        qknorm_rope_kernel<<<dim3(S_LEN, N_HEADS + N_KV), 128>>>(
            pqkv, qn + l * HEAD_DIM, kn + l * HEAD_DIM, cosb, sinb);

        attn_kernel<<<dim3(S_LEN / 32, N_HEADS), 128>>>(pqkv, pctx3);

        wconv_kernel<<<WB, WT>>>((const float2*)(o_w + (size_t)l * D_MODEL * 2048),
                                 wo, D_MODEL, 2048);

        hgemm3_kernel<1><<<dim3(D_MODEL / BN, S_LEN / BM), 256, GEMM_SMEM>>>(
            pctx3, wo, h, S_LEN, D_MODEL, K3_D);

        rmsnorm_t_kernel<<<S_LEN, 256>>>(h, ln2 + l * D_MODEL, px3);

        wconv_kernel<<<WB, WT>>>((const float2*)(gate_w + (size_t)l * INTER * D_MODEL),
                                 wg, INTER, D_MODEL);
        wconv_kernel<<<WB, WT>>>((const float2*)(up_w + (size_t)l * INTER * D_MODEL),
                                 wg + (size_t)INTER * K3_D, INTER, D_MODEL);

        hgemm3_kernel<0><<<dim3(GU_N / BN, S_LEN / BM), 256, GEMM_SMEM>>>(
            px3, wg, pgu, S_LEN, GU_N, K3_D);

        silumul_t_kernel<<<S_LEN, 256>>>(pgu, pm3);

        wconv_kernel<<<WB, WT>>>((const float2*)(down_w + (size_t)l * D_MODEL * INTER),
                                 wd, D_MODEL, INTER);

        hgemm3_kernel<1><<<dim3(D_MODEL / BN, S_LEN / BM), 256, GEMM_SMEM>>>(
            pm3, wd, h, S_LEN, D_MODEL, K3_I);
    }
}